// round 1
// baseline (speedup 1.0000x reference)
#include <cuda_runtime.h>

// ---------------------------------------------------------------------------
// FastAttention (linear attention, ReLU feature maps) — fp32 SIMT baseline
//
// Pipeline (all launched on default stream, graph-capturable, no allocs):
//   K1 build_weff : Wq_eff/Wk_eff = per-head (Wq^T @ P[h]) folded weights
//   K2 copy_wv    : append Wv rows into the fused weight matrix
//   K3 gemm_nt    : PHIV[16384,3072] = X @ WBIG^T, relu on cols [0,2048)
//                   (cols 0-1023 = phiQ, 1024-2047 = phiK, 2048-3071 = V)
//   K4 kv_kernel  : split-K partial kv[64x64] + ksum[64] per (b,h)
//   K5 kv_reduce  : deterministic reduction of split-K partials
//   K6 attn_kernel: attn = inv * phiQ @ kv   (inv = 1/(scale*denom + 1e-8))
//   K7 gemm_nt    : out[16384,1024] = ATTN @ Wo^T + bo
// ---------------------------------------------------------------------------

// ------------------------- device scratch (no allocs) ----------------------
__device__ float g_WBIG[(size_t)3072 * 1024];          // 12 MB fused weights
__device__ float g_PHIV[(size_t)16384 * 3072];         // 192 MB phiQ|phiK|V
__device__ float g_ATTN[(size_t)16384 * 1024];         // 64 MB
__device__ float g_KV[64 * 64 * 64];                   // kv per (b,h)
__device__ float g_KSUM[64 * 64];                      // ksum per (b,h)
__device__ float g_KVP[8 * 64 * 64 * 64];              // split-K partials
__device__ float g_KSP[8 * 64 * 64];

// ------------------------- K1: fused per-head weights -----------------------
// Weff[h*64+d'][d] = sum_e W[h*64+e][d] * P[h][e][d']
// grid 512 = {q,k} x 16 heads x 16 column-chunks of 64; 256 threads
__global__ __launch_bounds__(256)
void build_weff_kernel(const float* __restrict__ Wq,
                       const float* __restrict__ Wk,
                       const float* __restrict__ P)
{
    int bid   = blockIdx.x;
    int which = bid >> 8;           // 0 = q, 1 = k
    int rem   = bid & 255;
    int h     = rem >> 4;
    int chunk = rem & 15;           // 64-column chunk of d
    const float* W = which ? Wk : Wq;

    __shared__ float Psh[64][64];   // P[h][e][d']
    __shared__ float Wsh[64][64];   // W[h*64+e][chunk*64 + c]
    int tid = threadIdx.x;

#pragma unroll
    for (int i = 0; i < 4; i++) {
        int f = tid + i * 256;
        int e = f >> 4, c4 = (f & 15) << 2;
        *(float4*)&Psh[e][c4] = *(const float4*)(P + (size_t)h * 4096 + f * 4);
        *(float4*)&Wsh[e][c4] =
            *(const float4*)(W + (size_t)(h * 64 + e) * 1024 + chunk * 64 + c4);
    }
    __syncthreads();

    int dp = tid & 63;              // output row within head (d')
    int dg = tid >> 6;              // 0..3 -> 16 columns each
    float acc[16];
#pragma unroll
    for (int j = 0; j < 16; j++) acc[j] = 0.f;
#pragma unroll 4
    for (int e = 0; e < 64; e++) {
        float p = Psh[e][dp];
#pragma unroll
        for (int j = 0; j < 16; j++)
            acc[j] += p * Wsh[e][dg * 16 + j];
    }
    float* dst = g_WBIG + (size_t)(which * 1024 + h * 64 + dp) * 1024
                        + chunk * 64 + dg * 16;
#pragma unroll
    for (int j = 0; j < 16; j += 4)
        *(float4*)(dst + j) = make_float4(acc[j], acc[j + 1], acc[j + 2], acc[j + 3]);
}

// ------------------------- K2: copy Wv into WBIG ----------------------------
__global__ __launch_bounds__(256)
void copy_wv_kernel(const float* __restrict__ Wv)
{
    int row = blockIdx.x;
    int tid = threadIdx.x;
    *(float4*)(g_WBIG + (size_t)(2048 + row) * 1024 + tid * 4) =
        *(const float4*)(Wv + (size_t)row * 1024 + tid * 4);
}

// ------------------------- K3/K7: big NT GEMM -------------------------------
// C[M,N] = A[M,K] @ B[N,K]^T  (+bias, +relu on cols < relu_cols)
// 128x128x16 tiles, 256 threads, 8x8 micro-tile, double-buffered SMEM.
template<bool RELU, bool BIAS>
__global__ __launch_bounds__(256, 2)
void gemm_nt_kernel(const float* __restrict__ A, const float* __restrict__ Bm,
                    const float* __restrict__ bias, float* __restrict__ C,
                    int M, int N, int K, int relu_cols)
{
    __shared__ float As[2][16][132];
    __shared__ float Bs[2][16][132];
    const int tid = threadIdx.x;
    const int m0 = blockIdx.y * 128;
    const int n0 = blockIdx.x * 128;

    const int lr = tid >> 2;            // row 0..63 (and +64)
    const int lc = (tid & 3) << 2;      // k-col 0,4,8,12

    const float* Ag = A  + (size_t)(m0 + lr) * K + lc;
    const float* Bg = Bm + (size_t)(n0 + lr) * K + lc;
    const size_t rstep = (size_t)64 * K;

    float4 pa0 = *(const float4*)(Ag);
    float4 pa1 = *(const float4*)(Ag + rstep);
    float4 pb0 = *(const float4*)(Bg);
    float4 pb1 = *(const float4*)(Bg + rstep);

#pragma unroll
    for (int j = 0; j < 4; j++) {
        As[0][lc + j][lr]      = ((float*)&pa0)[j];
        As[0][lc + j][lr + 64] = ((float*)&pa1)[j];
        Bs[0][lc + j][lr]      = ((float*)&pb0)[j];
        Bs[0][lc + j][lr + 64] = ((float*)&pb1)[j];
    }
    __syncthreads();

    const int ty = tid >> 4;
    const int tx = tid & 15;
    float acc[8][8];
#pragma unroll
    for (int i = 0; i < 8; i++)
#pragma unroll
        for (int j = 0; j < 8; j++) acc[i][j] = 0.f;

    const int ktiles = K >> 4;
    int cur = 0;
    for (int kt = 0; kt < ktiles; kt++) {
        if (kt + 1 < ktiles) {
            const float* Ag2 = Ag + (kt + 1) * 16;
            const float* Bg2 = Bg + (kt + 1) * 16;
            pa0 = *(const float4*)(Ag2);
            pa1 = *(const float4*)(Ag2 + rstep);
            pb0 = *(const float4*)(Bg2);
            pb1 = *(const float4*)(Bg2 + rstep);
        }
#pragma unroll
        for (int k = 0; k < 16; k++) {
            float ar[8], br[8];
            *(float4*)&ar[0] = *(float4*)&As[cur][k][ty * 4];
            *(float4*)&ar[4] = *(float4*)&As[cur][k][64 + ty * 4];
            *(float4*)&br[0] = *(float4*)&Bs[cur][k][tx * 4];
            *(float4*)&br[4] = *(float4*)&Bs[cur][k][64 + tx * 4];
#pragma unroll
            for (int i = 0; i < 8; i++)
#pragma unroll
                for (int j = 0; j < 8; j++)
                    acc[i][j] += ar[i] * br[j];
        }
        if (kt + 1 < ktiles) {
            int nxt = cur ^ 1;
#pragma unroll
            for (int j = 0; j < 4; j++) {
                As[nxt][lc + j][lr]      = ((float*)&pa0)[j];
                As[nxt][lc + j][lr + 64] = ((float*)&pa1)[j];
                Bs[nxt][lc + j][lr]      = ((float*)&pb0)[j];
                Bs[nxt][lc + j][lr + 64] = ((float*)&pb1)[j];
            }
            __syncthreads();
            cur = nxt;
        }
    }

#pragma unroll
    for (int i = 0; i < 8; i++) {
        int rloc = (i < 4) ? (ty * 4 + i) : (64 + ty * 4 + (i - 4));
        size_t rowoff = (size_t)(m0 + rloc) * N;
#pragma unroll
        for (int jh = 0; jh < 2; jh++) {
            int col = n0 + (jh ? 64 + tx * 4 : tx * 4);
            float4 v = make_float4(acc[i][jh * 4 + 0], acc[i][jh * 4 + 1],
                                   acc[i][jh * 4 + 2], acc[i][jh * 4 + 3]);
            if (BIAS) {
                v.x += bias[col + 0]; v.y += bias[col + 1];
                v.z += bias[col + 2]; v.w += bias[col + 3];
            }
            if (RELU && col < relu_cols) {
                v.x = fmaxf(v.x, 0.f); v.y = fmaxf(v.y, 0.f);
                v.z = fmaxf(v.z, 0.f); v.w = fmaxf(v.w, 0.f);
            }
            *(float4*)(C + rowoff + col) = v;
        }
    }
}

// ------------------------- K4: kv + ksum (split-K partials) -----------------
// grid (8 splits, 64 bh), 256 threads; each block reduces 512 rows.
__global__ __launch_bounds__(256)
void kv_kernel()
{
    int split = blockIdx.x;
    int bh = blockIdx.y;
    int b = bh >> 4, h = bh & 15;
    __shared__ float PK[64][68];
    __shared__ float VV[64][68];
    int tid = threadIdx.x;
    int ti = tid >> 4, tj = tid & 15;

    float acc[4][4];
#pragma unroll
    for (int i = 0; i < 4; i++)
#pragma unroll
        for (int j = 0; j < 4; j++) acc[i][j] = 0.f;
    float ks = 0.f;

    size_t base_row = (size_t)b * 4096 + split * 512;
    for (int c = 0; c < 8; c++) {
#pragma unroll
        for (int i = 0; i < 4; i++) {
            int f = tid + i * 256;
            int r = f >> 4, c4 = (f & 15) << 2;
            const float* src = g_PHIV + (base_row + c * 64 + r) * 3072;
            *(float4*)&PK[r][c4] = *(const float4*)(src + 1024 + h * 64 + c4);
            *(float4*)&VV[r][c4] = *(const float4*)(src + 2048 + h * 64 + c4);
        }
        __syncthreads();
#pragma unroll 8
        for (int n = 0; n < 64; n++) {
            float4 a  = *(float4*)&PK[n][ti * 4];
            float4 bb = *(float4*)&VV[n][tj * 4];
            float av[4] = {a.x, a.y, a.z, a.w};
            float bv[4] = {bb.x, bb.y, bb.z, bb.w};
#pragma unroll
            for (int i = 0; i < 4; i++)
#pragma unroll
                for (int j = 0; j < 4; j++)
                    acc[i][j] += av[i] * bv[j];
        }
        if (tid < 64) {
#pragma unroll 8
            for (int n = 0; n < 64; n++) ks += PK[n][tid];
        }
        __syncthreads();
    }
    float* dst = g_KVP + (size_t)(split * 64 + bh) * 4096;
#pragma unroll
    for (int i = 0; i < 4; i++)
#pragma unroll
        for (int j = 0; j < 4; j++)
            dst[(ti * 4 + i) * 64 + tj * 4 + j] = acc[i][j];
    if (tid < 64) g_KSP[(split * 64 + bh) * 64 + tid] = ks;
}

// ------------------------- K5: deterministic reduction ----------------------
__global__ __launch_bounds__(256)
void kv_reduce_kernel()
{
    int idx = blockIdx.x * 256 + threadIdx.x;
    if (idx < 64 * 4096) {
        int bh = idx >> 12, r = idx & 4095;
        float s = 0.f;
#pragma unroll
        for (int sp = 0; sp < 8; sp++)
            s += g_KVP[(size_t)(sp * 64 + bh) * 4096 + r];
        g_KV[idx] = s;
    } else {
        int j = idx - 64 * 4096;
        if (j < 64 * 64) {
            int bh = j >> 6, d = j & 63;
            float s = 0.f;
#pragma unroll
            for (int sp = 0; sp < 8; sp++)
                s += g_KSP[(sp * 64 + bh) * 64 + d];
            g_KSUM[j] = s;
        }
    }
}

// ------------------------- K6: attn = inv * phiQ @ kv -----------------------
// grid (32 row-chunks of 128, 64 bh), 256 threads (2 threads per row).
__global__ __launch_bounds__(256)
void attn_kernel()
{
    int chunkb = blockIdx.x;
    int bh = blockIdx.y;
    int b = bh >> 4, h = bh & 15;
    __shared__ float KVs[64][64];
    __shared__ float KSs[64];
    int tid = threadIdx.x;
#pragma unroll
    for (int i = 0; i < 4; i++) {
        int f = tid + i * 256;
        *(float4*)&KVs[f >> 4][(f & 15) << 2] =
            *(const float4*)(g_KV + (size_t)bh * 4096 + f * 4);
    }
    if (tid < 64) KSs[tid] = g_KSUM[bh * 64 + tid];
    __syncthreads();

    int r = tid >> 1, half = tid & 1;
    size_t m = (size_t)b * 4096 + chunkb * 128 + r;
    const float* phq = g_PHIV + m * 3072 + h * 64;

    float acc[32];
#pragma unroll
    for (int j = 0; j < 32; j++) acc[j] = 0.f;
    float denom = 0.f;

#pragma unroll
    for (int d0 = 0; d0 < 64; d0 += 16) {
        float q[16];
#pragma unroll
        for (int i = 0; i < 4; i++)
            *(float4*)&q[i * 4] = *(const float4*)(phq + d0 + i * 4);
#pragma unroll
        for (int dd = 0; dd < 16; dd++) {
            int d = d0 + dd;
            float p = q[dd];
            denom += p * KSs[d];
#pragma unroll
            for (int j = 0; j < 32; j += 4) {
                float4 kvv = *(float4*)&KVs[d][half * 32 + j];
                acc[j]     += p * kvv.x;
                acc[j + 1] += p * kvv.y;
                acc[j + 2] += p * kvv.z;
                acc[j + 3] += p * kvv.w;
            }
        }
    }
    float inv = 1.0f / (0.125f * denom + 1e-8f);   // scale = 1/sqrt(64)
    float* dst = g_ATTN + m * 1024 + h * 64 + half * 32;
#pragma unroll
    for (int j = 0; j < 32; j += 4)
        *(float4*)(dst + j) = make_float4(acc[j] * inv, acc[j + 1] * inv,
                                          acc[j + 2] * inv, acc[j + 3] * inv);
}

// ------------------------- launch -------------------------------------------
extern "C" void kernel_launch(void* const* d_in, const int* in_sizes, int n_in,
                              void* d_out, int out_size)
{
    const float* query = (const float*)d_in[0];
    const float* Wq    = (const float*)d_in[1];
    const float* Wk    = (const float*)d_in[2];
    const float* Wv    = (const float*)d_in[3];
    const float* P     = (const float*)d_in[4];
    const float* Wo    = (const float*)d_in[5];
    const float* bo    = (const float*)d_in[6];
    float* out = (float*)d_out;

    void *p_wbig, *p_phiv, *p_attn;
    cudaGetSymbolAddress(&p_wbig, g_WBIG);
    cudaGetSymbolAddress(&p_phiv, g_PHIV);
    cudaGetSymbolAddress(&p_attn, g_ATTN);

    build_weff_kernel<<<512, 256>>>(Wq, Wk, P);
    copy_wv_kernel<<<1024, 256>>>(Wv);

    // PHIV = relu(X @ WBIG^T) on first 2048 cols, plain on V cols
    gemm_nt_kernel<true, false><<<dim3(24, 128), 256>>>(
        query, (const float*)p_wbig, nullptr, (float*)p_phiv,
        16384, 3072, 1024, 2048);

    kv_kernel<<<dim3(8, 64), 256>>>();
    kv_reduce_kernel<<<1040, 256>>>();
    attn_kernel<<<dim3(32, 64), 256>>>();

    // out = ATTN @ Wo^T + bo
    gemm_nt_kernel<false, true><<<dim3(8, 128), 256>>>(
        (const float*)p_attn, Wo, bo, out,
        16384, 1024, 1024, 0);
}

// round 3
// speedup vs baseline: 2.5093x; 2.5093x over previous
#include <cuda_runtime.h>
#include <cstdint>

// ---------------------------------------------------------------------------
// FastAttention — linear attention with ReLU feature maps.
// Big GEMMs on tf32 mma.sync (sm_100 baseline-legal), rest fp32 SIMT.
//
//   K1 build_weff : fold per-head orth proj into Wq/Wk (tf32-rounded output)
//   K2 copy_wv    : append Wv rows (tf32-rounded)
//   R1 round      : query -> tf32-rounded copy (into g_ATTN buffer)
//   R2 round      : Wo -> g_WOR tf32-rounded
//   G1 gemm_mma   : PHIV[16384,3072] = Xr @ WBIG^T, relu on cols [0,2048)
//   K4 kv_kernel  : split-K partial kv[64x64] + ksum[64] per (b,h)
//   K5 kv_reduce  : deterministic reduction
//   K6 attn_kernel: attn = inv * phiQ @ kv (tf32-rounded output)
//   G2 gemm_mma   : out = ATTN @ WOR^T + bo
// ---------------------------------------------------------------------------

// ------------------------- device scratch (no allocs) ----------------------
__device__ float g_WBIG[(size_t)3072 * 1024];
__device__ float g_PHIV[(size_t)16384 * 3072];
__device__ float g_ATTN[(size_t)16384 * 1024];   // rounded query, later attn
__device__ float g_WOR[(size_t)1024 * 1024];
__device__ float g_KV[64 * 64 * 64];
__device__ float g_KSUM[64 * 64];
__device__ float g_KVP[8 * 64 * 64 * 64];
__device__ float g_KSP[8 * 64 * 64];

// ------------------------- helpers ------------------------------------------
__device__ __forceinline__ float to_tf32(float x) {
    uint32_t u;
    asm("cvt.rna.tf32.f32 %0, %1;" : "=r"(u) : "f"(x));
    return __uint_as_float(u);
}
__device__ __forceinline__ uint32_t smem_u32(const void* p) {
    uint32_t a;
    asm("{ .reg .u64 t; cvta.to.shared.u64 t, %1; cvt.u32.u64 %0, t; }"
        : "=r"(a) : "l"(p));
    return a;
}
__device__ __forceinline__ void cp16(uint32_t dst, const void* src) {
    asm volatile("cp.async.cg.shared.global [%0], [%1], 16;" :: "r"(dst), "l"(src));
}
__device__ __forceinline__ void mma_tf32(float* c, uint32_t a0, uint32_t a1,
                                         uint32_t a2, uint32_t a3,
                                         uint32_t b0, uint32_t b1) {
    asm volatile(
        "mma.sync.aligned.m16n8k8.row.col.f32.tf32.tf32.f32 "
        "{%0,%1,%2,%3}, {%4,%5,%6,%7}, {%8,%9}, {%0,%1,%2,%3};"
        : "+f"(c[0]), "+f"(c[1]), "+f"(c[2]), "+f"(c[3])
        : "r"(a0), "r"(a1), "r"(a2), "r"(a3), "r"(b0), "r"(b1));
}

// ------------------------- K1: fused per-head weights -----------------------
__global__ __launch_bounds__(256)
void build_weff_kernel(const float* __restrict__ Wq,
                       const float* __restrict__ Wk,
                       const float* __restrict__ P)
{
    int bid   = blockIdx.x;
    int which = bid >> 8;
    int rem   = bid & 255;
    int h     = rem >> 4;
    int chunk = rem & 15;
    const float* W = which ? Wk : Wq;

    __shared__ float Psh[64][64];
    __shared__ float Wsh[64][64];
    int tid = threadIdx.x;

#pragma unroll
    for (int i = 0; i < 4; i++) {
        int f = tid + i * 256;
        int e = f >> 4, c4 = (f & 15) << 2;
        *(float4*)&Psh[e][c4] = *(const float4*)(P + (size_t)h * 4096 + f * 4);
        *(float4*)&Wsh[e][c4] =
            *(const float4*)(W + (size_t)(h * 64 + e) * 1024 + chunk * 64 + c4);
    }
    __syncthreads();

    int dp = tid & 63;
    int dg = tid >> 6;
    float acc[16];
#pragma unroll
    for (int j = 0; j < 16; j++) acc[j] = 0.f;
#pragma unroll 4
    for (int e = 0; e < 64; e++) {
        float p = Psh[e][dp];
#pragma unroll
        for (int j = 0; j < 16; j++)
            acc[j] += p * Wsh[e][dg * 16 + j];
    }
    float* dst = g_WBIG + (size_t)(which * 1024 + h * 64 + dp) * 1024
                        + chunk * 64 + dg * 16;
#pragma unroll
    for (int j = 0; j < 16; j += 4)
        *(float4*)(dst + j) = make_float4(to_tf32(acc[j]), to_tf32(acc[j + 1]),
                                          to_tf32(acc[j + 2]), to_tf32(acc[j + 3]));
}

// ------------------------- K2: copy Wv (tf32-rounded) ------------------------
__global__ __launch_bounds__(256)
void copy_wv_kernel(const float* __restrict__ Wv)
{
    int row = blockIdx.x;
    int tid = threadIdx.x;
    float4 v = *(const float4*)(Wv + (size_t)row * 1024 + tid * 4);
    v = make_float4(to_tf32(v.x), to_tf32(v.y), to_tf32(v.z), to_tf32(v.w));
    *(float4*)(g_WBIG + (size_t)(2048 + row) * 1024 + tid * 4) = v;
}

// ------------------------- round fp32 -> tf32 --------------------------------
__global__ __launch_bounds__(256)
void round_tf32_kernel(const float* __restrict__ src, float* __restrict__ dst)
{
    size_t i = ((size_t)blockIdx.x * 256 + threadIdx.x) * 4;
    float4 v = *(const float4*)(src + i);
    v = make_float4(to_tf32(v.x), to_tf32(v.y), to_tf32(v.z), to_tf32(v.w));
    *(float4*)(dst + i) = v;
}

// ------------------------- tf32 mma.sync GEMM -------------------------------
// C[M,N] = A[M,K] @ B[N,K]^T (+bias, +relu on cols < relu_cols)
// CTA tile 128x128x32, 256 threads (8 warps, 2x4), warp tile 64x32.
// 3-stage cp.async ring; SMEM rows padded to 36 floats (conflict-free lds).
constexpr int GS_STRIDE = 36;                       // floats per smem row
constexpr int GS_TILE   = 128 * GS_STRIDE;          // floats per A (or B) tile
constexpr int GS_STAGE  = 2 * GS_TILE;              // A + B
constexpr int G_STAGES  = 3;
constexpr int GEMM_SMEM = G_STAGES * GS_STAGE * 4;  // bytes = 110592

template<bool RELU, bool BIAS>
__global__ __launch_bounds__(256, 2)
void gemm_mma(const float* __restrict__ A, const float* __restrict__ Bm,
              const float* __restrict__ bias, float* __restrict__ C,
              int M, int N, int K, int relu_cols)
{
    extern __shared__ float smem[];
    const int tid = threadIdx.x;
    const int m0 = blockIdx.y * 128;
    const int n0 = blockIdx.x * 128;
    const int KT = K >> 5;

    const uint32_t smem_base = smem_u32(smem);

    // ---- async tile loader: chunk kt -> stage buffer ----
    auto load_stage = [&](int kt, int buf) {
        uint32_t ab = smem_base + buf * (GS_STAGE * 4);
        uint32_t bb = ab + GS_TILE * 4;
        const float* Asrc = A + (size_t)m0 * K + kt * 32;
        const float* Bsrc = Bm + (size_t)n0 * K + kt * 32;
#pragma unroll
        for (int j = 0; j < 4; j++) {
            int o = tid + j * 256;              // 1024 chunks of 16B
            int r = o >> 3, cc = o & 7;
            cp16(ab + (uint32_t)(r * GS_STRIDE + cc * 4) * 4,
                 Asrc + (size_t)r * K + cc * 4);
            cp16(bb + (uint32_t)(r * GS_STRIDE + cc * 4) * 4,
                 Bsrc + (size_t)r * K + cc * 4);
        }
    };

    // warp coordinates
    const int wid = tid >> 5;
    const int lane = tid & 31;
    const int wm = wid & 1;                     // 0..1  (64 rows each)
    const int wn = wid >> 1;                    // 0..3  (32 cols each)
    const int g  = lane >> 2;                   // group id 0..7
    const int tg = lane & 3;                    // thread-in-group

    float acc[4][4][4];
#pragma unroll
    for (int mi = 0; mi < 4; mi++)
#pragma unroll
        for (int ni = 0; ni < 4; ni++)
#pragma unroll
            for (int q = 0; q < 4; q++) acc[mi][ni][q] = 0.f;

    // prologue: stages 0,1
    load_stage(0, 0);
    asm volatile("cp.async.commit_group;" ::: "memory");
    load_stage(1, 1);
    asm volatile("cp.async.commit_group;" ::: "memory");

    for (int kt = 0; kt < KT; kt++) {
        asm volatile("cp.async.wait_group 1;" ::: "memory");
        __syncthreads();

        if (kt + 2 < KT) load_stage(kt + 2, (kt + 2) % G_STAGES);
        asm volatile("cp.async.commit_group;" ::: "memory");

        const float* As = smem + (kt % G_STAGES) * GS_STAGE;
        const float* Bs = As + GS_TILE;

#pragma unroll
        for (int ks = 0; ks < 4; ks++) {
            const int k0 = ks * 8;
            uint32_t af[4][4];
#pragma unroll
            for (int mi = 0; mi < 4; mi++) {
                const float* ap = As + (wm * 64 + mi * 16 + g) * GS_STRIDE + k0 + tg;
                af[mi][0] = __float_as_uint(ap[0]);
                af[mi][1] = __float_as_uint(ap[8 * GS_STRIDE]);
                af[mi][2] = __float_as_uint(ap[4]);
                af[mi][3] = __float_as_uint(ap[8 * GS_STRIDE + 4]);
            }
            uint32_t bf[4][2];
#pragma unroll
            for (int ni = 0; ni < 4; ni++) {
                const float* bp = Bs + (wn * 32 + ni * 8 + g) * GS_STRIDE + k0 + tg;
                bf[ni][0] = __float_as_uint(bp[0]);
                bf[ni][1] = __float_as_uint(bp[4]);
            }
#pragma unroll
            for (int mi = 0; mi < 4; mi++)
#pragma unroll
                for (int ni = 0; ni < 4; ni++)
                    mma_tf32(acc[mi][ni], af[mi][0], af[mi][1], af[mi][2],
                             af[mi][3], bf[ni][0], bf[ni][1]);
        }
        __syncthreads();
    }

    // ---- epilogue ----
#pragma unroll
    for (int mi = 0; mi < 4; mi++) {
        int row0 = m0 + wm * 64 + mi * 16 + g;
#pragma unroll
        for (int ni = 0; ni < 4; ni++) {
            int col = n0 + wn * 32 + ni * 8 + tg * 2;
            float2 v0 = make_float2(acc[mi][ni][0], acc[mi][ni][1]);
            float2 v1 = make_float2(acc[mi][ni][2], acc[mi][ni][3]);
            if (BIAS) {
                float2 b2 = *(const float2*)(bias + col);
                v0.x += b2.x; v0.y += b2.y;
                v1.x += b2.x; v1.y += b2.y;
            }
            if (RELU && col < relu_cols) {
                v0.x = fmaxf(v0.x, 0.f); v0.y = fmaxf(v0.y, 0.f);
                v1.x = fmaxf(v1.x, 0.f); v1.y = fmaxf(v1.y, 0.f);
            }
            *(float2*)(C + (size_t)row0 * N + col) = v0;
            *(float2*)(C + (size_t)(row0 + 8) * N + col) = v1;
        }
    }
}

// ------------------------- K4: kv + ksum (split-K partials) -----------------
__global__ __launch_bounds__(256)
void kv_kernel()
{
    int split = blockIdx.x;
    int bh = blockIdx.y;
    int b = bh >> 4, h = bh & 15;
    __shared__ float PK[64][68];
    __shared__ float VV[64][68];
    int tid = threadIdx.x;
    int ti = tid >> 4, tj = tid & 15;

    float acc[4][4];
#pragma unroll
    for (int i = 0; i < 4; i++)
#pragma unroll
        for (int j = 0; j < 4; j++) acc[i][j] = 0.f;
    float ks = 0.f;

    size_t base_row = (size_t)b * 4096 + split * 512;
    for (int c = 0; c < 8; c++) {
#pragma unroll
        for (int i = 0; i < 4; i++) {
            int f = tid + i * 256;
            int r = f >> 4, c4 = (f & 15) << 2;
            const float* src = g_PHIV + (base_row + c * 64 + r) * 3072;
            *(float4*)&PK[r][c4] = *(const float4*)(src + 1024 + h * 64 + c4);
            *(float4*)&VV[r][c4] = *(const float4*)(src + 2048 + h * 64 + c4);
        }
        __syncthreads();
#pragma unroll 8
        for (int n = 0; n < 64; n++) {
            float4 a  = *(float4*)&PK[n][ti * 4];
            float4 bb = *(float4*)&VV[n][tj * 4];
            float av[4] = {a.x, a.y, a.z, a.w};
            float bv[4] = {bb.x, bb.y, bb.z, bb.w};
#pragma unroll
            for (int i = 0; i < 4; i++)
#pragma unroll
                for (int j = 0; j < 4; j++)
                    acc[i][j] += av[i] * bv[j];
        }
        if (tid < 64) {
#pragma unroll 8
            for (int n = 0; n < 64; n++) ks += PK[n][tid];
        }
        __syncthreads();
    }
    float* dst = g_KVP + (size_t)(split * 64 + bh) * 4096;
#pragma unroll
    for (int i = 0; i < 4; i++)
#pragma unroll
        for (int j = 0; j < 4; j++)
            dst[(ti * 4 + i) * 64 + tj * 4 + j] = acc[i][j];
    if (tid < 64) g_KSP[(split * 64 + bh) * 64 + tid] = ks;
}

// ------------------------- K5: deterministic reduction ----------------------
__global__ __launch_bounds__(256)
void kv_reduce_kernel()
{
    int idx = blockIdx.x * 256 + threadIdx.x;
    if (idx < 64 * 4096) {
        int bh = idx >> 12, r = idx & 4095;
        float s = 0.f;
#pragma unroll
        for (int sp = 0; sp < 8; sp++)
            s += g_KVP[(size_t)(sp * 64 + bh) * 4096 + r];
        g_KV[idx] = s;
    } else {
        int j = idx - 64 * 4096;
        if (j < 64 * 64) {
            int bh = j >> 6, d = j & 63;
            float s = 0.f;
#pragma unroll
            for (int sp = 0; sp < 8; sp++)
                s += g_KSP[(sp * 64 + bh) * 64 + d];
            g_KSUM[j] = s;
        }
    }
}

// ------------------------- K6: attn = inv * phiQ @ kv (tf32 out) ------------
__global__ __launch_bounds__(256)
void attn_kernel()
{
    int chunkb = blockIdx.x;
    int bh = blockIdx.y;
    int b = bh >> 4, h = bh & 15;
    __shared__ float KVs[64][64];
    __shared__ float KSs[64];
    int tid = threadIdx.x;
#pragma unroll
    for (int i = 0; i < 4; i++) {
        int f = tid + i * 256;
        *(float4*)&KVs[f >> 4][(f & 15) << 2] =
            *(const float4*)(g_KV + (size_t)bh * 4096 + f * 4);
    }
    if (tid < 64) KSs[tid] = g_KSUM[bh * 64 + tid];
    __syncthreads();

    int r = tid >> 1, half = tid & 1;
    size_t m = (size_t)b * 4096 + chunkb * 128 + r;
    const float* phq = g_PHIV + m * 3072 + h * 64;

    float acc[32];
#pragma unroll
    for (int j = 0; j < 32; j++) acc[j] = 0.f;
    float denom = 0.f;

#pragma unroll
    for (int d0 = 0; d0 < 64; d0 += 16) {
        float q[16];
#pragma unroll
        for (int i = 0; i < 4; i++)
            *(float4*)&q[i * 4] = *(const float4*)(phq + d0 + i * 4);
#pragma unroll
        for (int dd = 0; dd < 16; dd++) {
            int d = d0 + dd;
            float p = q[dd];
            denom += p * KSs[d];
#pragma unroll
            for (int j = 0; j < 32; j += 4) {
                float4 kvv = *(float4*)&KVs[d][half * 32 + j];
                acc[j]     += p * kvv.x;
                acc[j + 1] += p * kvv.y;
                acc[j + 2] += p * kvv.z;
                acc[j + 3] += p * kvv.w;
            }
        }
    }
    float inv = 1.0f / (0.125f * denom + 1e-8f);
    float* dst = g_ATTN + m * 1024 + h * 64 + half * 32;
#pragma unroll
    for (int j = 0; j < 32; j += 4)
        *(float4*)(dst + j) = make_float4(
            to_tf32(acc[j] * inv), to_tf32(acc[j + 1] * inv),
            to_tf32(acc[j + 2] * inv), to_tf32(acc[j + 3] * inv));
}

// ------------------------- launch -------------------------------------------
extern "C" void kernel_launch(void* const* d_in, const int* in_sizes, int n_in,
                              void* d_out, int out_size)
{
    const float* query = (const float*)d_in[0];
    const float* Wq    = (const float*)d_in[1];
    const float* Wk    = (const float*)d_in[2];
    const float* Wv    = (const float*)d_in[3];
    const float* P     = (const float*)d_in[4];
    const float* Wo    = (const float*)d_in[5];
    const float* bo    = (const float*)d_in[6];
    float* out = (float*)d_out;

    void *p_wbig, *p_phiv, *p_attn, *p_wor;
    cudaGetSymbolAddress(&p_wbig, g_WBIG);
    cudaGetSymbolAddress(&p_phiv, g_PHIV);
    cudaGetSymbolAddress(&p_attn, g_ATTN);
    cudaGetSymbolAddress(&p_wor,  g_WOR);

    cudaFuncSetAttribute(gemm_mma<true, false>,
                         cudaFuncAttributeMaxDynamicSharedMemorySize, GEMM_SMEM);
    cudaFuncSetAttribute(gemm_mma<false, true>,
                         cudaFuncAttributeMaxDynamicSharedMemorySize, GEMM_SMEM);

    build_weff_kernel<<<512, 256>>>(Wq, Wk, P);
    copy_wv_kernel<<<1024, 256>>>(Wv);
    round_tf32_kernel<<<16384, 256>>>(query, (float*)p_attn);
    round_tf32_kernel<<<1024, 256>>>(Wo, (float*)p_wor);

    // PHIV = relu(Xr @ WBIG^T) on first 2048 cols
    gemm_mma<true, false><<<dim3(24, 128), 256, GEMM_SMEM>>>(
        (const float*)p_attn, (const float*)p_wbig, nullptr, (float*)p_phiv,
        16384, 3072, 1024, 2048);

    kv_kernel<<<dim3(8, 64), 256>>>();
    kv_reduce_kernel<<<1040, 256>>>();
    attn_kernel<<<dim3(32, 64), 256>>>();   // writes tf32-rounded ATTN

    // out = ATTN @ WOR^T + bo
    gemm_mma<false, true><<<dim3(8, 128), 256, GEMM_SMEM>>>(
        (const float*)p_attn, (const float*)p_wor, bo, out,
        16384, 1024, 1024, 0);
}

// round 4
// speedup vs baseline: 3.8414x; 1.5309x over previous
#include <cuda_runtime.h>
#include <cuda_fp16.h>
#include <cstdint>

// ---------------------------------------------------------------------------
// FastAttention — linear attention with ReLU feature maps.
// Big GEMMs: fp16 mma.sync (m16n8k16, fp32 accum). Small kernels fp32 SIMT.
//
//   K1 build_weff : fold per-head orth proj into Wq/Wk -> g_WBIGH (fp16)
//   K2 copy_wv    : append Wv rows (fp16)
//   R1 round      : query -> g_XH (fp16)
//   R2 round      : Wo -> g_WORH (fp16)
//   G1 gemm_mma   : PHIV[16384,3072](fp32) = XH @ WBIGH^T, relu cols [0,2048)
//   K4 kv_kernel  : split-K partial kv[64x64] + ksum[64] per (b,h)
//   K5 kv_reduce  : deterministic reduction
//   K6 attn_kernel: attn = inv * phiQ @ kv -> g_ATTNH (fp16)
//   G2 gemm_mma   : out(fp32) = ATTNH @ WORH^T + bo
// ---------------------------------------------------------------------------

// ------------------------- device scratch (no allocs) ----------------------
__device__ __align__(16) __half g_XH[(size_t)16384 * 1024];
__device__ __align__(16) __half g_WBIGH[(size_t)3072 * 1024];
__device__ __align__(16) __half g_WORH[(size_t)1024 * 1024];
__device__ __align__(16) __half g_ATTNH[(size_t)16384 * 1024];
__device__ float g_PHIV[(size_t)16384 * 3072];
__device__ float g_KV[64 * 64 * 64];
__device__ float g_KSUM[64 * 64];
__device__ float g_KVP[8 * 64 * 64 * 64];
__device__ float g_KSP[8 * 64 * 64];

// ------------------------- helpers ------------------------------------------
__device__ __forceinline__ uint32_t smem_u32(const void* p) {
    uint32_t a;
    asm("{ .reg .u64 t; cvta.to.shared.u64 t, %1; cvt.u32.u64 %0, t; }"
        : "=r"(a) : "l"(p));
    return a;
}
__device__ __forceinline__ void cp16(uint32_t dst, const void* src) {
    asm volatile("cp.async.cg.shared.global [%0], [%1], 16;" :: "r"(dst), "l"(src));
}
__device__ __forceinline__ void ldsm_x4(uint32_t& r0, uint32_t& r1,
                                        uint32_t& r2, uint32_t& r3, uint32_t a) {
    asm volatile("ldmatrix.sync.aligned.m8n8.x4.shared.b16 {%0,%1,%2,%3}, [%4];"
                 : "=r"(r0), "=r"(r1), "=r"(r2), "=r"(r3) : "r"(a));
}
__device__ __forceinline__ void ldsm_x2(uint32_t& r0, uint32_t& r1, uint32_t a) {
    asm volatile("ldmatrix.sync.aligned.m8n8.x2.shared.b16 {%0,%1}, [%2];"
                 : "=r"(r0), "=r"(r1) : "r"(a));
}
__device__ __forceinline__ void mma_f16(float* c, uint32_t a0, uint32_t a1,
                                        uint32_t a2, uint32_t a3,
                                        uint32_t b0, uint32_t b1) {
    asm volatile(
        "mma.sync.aligned.m16n8k16.row.col.f32.f16.f16.f32 "
        "{%0,%1,%2,%3}, {%4,%5,%6,%7}, {%8,%9}, {%0,%1,%2,%3};"
        : "+f"(c[0]), "+f"(c[1]), "+f"(c[2]), "+f"(c[3])
        : "r"(a0), "r"(a1), "r"(a2), "r"(a3), "r"(b0), "r"(b1));
}

// ------------------------- K1: fused per-head weights (fp16 out) ------------
__global__ __launch_bounds__(256)
void build_weff_kernel(const float* __restrict__ Wq,
                       const float* __restrict__ Wk,
                       const float* __restrict__ P)
{
    int bid   = blockIdx.x;
    int which = bid >> 8;
    int rem   = bid & 255;
    int h     = rem >> 4;
    int chunk = rem & 15;
    const float* W = which ? Wk : Wq;

    __shared__ float Psh[64][64];
    __shared__ float Wsh[64][64];
    int tid = threadIdx.x;

#pragma unroll
    for (int i = 0; i < 4; i++) {
        int f = tid + i * 256;
        int e = f >> 4, c4 = (f & 15) << 2;
        *(float4*)&Psh[e][c4] = *(const float4*)(P + (size_t)h * 4096 + f * 4);
        *(float4*)&Wsh[e][c4] =
            *(const float4*)(W + (size_t)(h * 64 + e) * 1024 + chunk * 64 + c4);
    }
    __syncthreads();

    int dp = tid & 63;
    int dg = tid >> 6;
    float acc[16];
#pragma unroll
    for (int j = 0; j < 16; j++) acc[j] = 0.f;
#pragma unroll 4
    for (int e = 0; e < 64; e++) {
        float p = Psh[e][dp];
#pragma unroll
        for (int j = 0; j < 16; j++)
            acc[j] += p * Wsh[e][dg * 16 + j];
    }
    __half* dst = g_WBIGH + (size_t)(which * 1024 + h * 64 + dp) * 1024
                          + chunk * 64 + dg * 16;
#pragma unroll
    for (int j = 0; j < 16; j += 2)
        *(half2*)(dst + j) = __floats2half2_rn(acc[j], acc[j + 1]);
}

// ------------------------- K2: copy Wv (fp16) --------------------------------
__global__ __launch_bounds__(256)
void copy_wv_kernel(const float* __restrict__ Wv)
{
    int row = blockIdx.x;
    int tid = threadIdx.x;
    float4 v = *(const float4*)(Wv + (size_t)row * 1024 + tid * 4);
    __half* dst = g_WBIGH + (size_t)(2048 + row) * 1024 + tid * 4;
    *(half2*)(dst)     = __floats2half2_rn(v.x, v.y);
    *(half2*)(dst + 2) = __floats2half2_rn(v.z, v.w);
}

// ------------------------- round fp32 -> fp16 --------------------------------
__global__ __launch_bounds__(256)
void round_half_kernel(const float* __restrict__ src, __half* __restrict__ dst)
{
    size_t i = ((size_t)blockIdx.x * 256 + threadIdx.x) * 4;
    float4 v = *(const float4*)(src + i);
    *(half2*)(dst + i)     = __floats2half2_rn(v.x, v.y);
    *(half2*)(dst + i + 2) = __floats2half2_rn(v.z, v.w);
}

// ------------------------- fp16 mma GEMM ------------------------------------
// C[M,N](fp32) = A[M,K] @ B[N,K]^T (+bias, +relu on cols < relu_cols)
// CTA tile 128x128x32, 256 threads (8 warps 2x4), warp tile 64x32.
// 3-stage cp.async ring; SMEM rows 32 halfs + pad -> 80B stride.
constexpr int HROW_B   = 80;                       // bytes per padded row
constexpr int H_TILE_B = 128 * HROW_B;             // 10240 B per A (or B) tile
constexpr int H_STAGE  = 2 * H_TILE_B;             // 20480
constexpr int H_STAGES = 3;
constexpr int GEMM_SMEM = H_STAGES * H_STAGE;      // 61440 B

template<bool RELU, bool BIAS>
__global__ __launch_bounds__(256, 2)
void gemm_mma(const __half* __restrict__ A, const __half* __restrict__ Bm,
              const float* __restrict__ bias, float* __restrict__ C,
              int M, int N, int K, int relu_cols)
{
    extern __shared__ char smem[];
    const int tid = threadIdx.x;
    const int m0 = blockIdx.y * 128;
    const int n0 = blockIdx.x * 128;
    const int KT = K >> 5;                         // chunks of 32 halfs

    const uint32_t smem_base = smem_u32(smem);

    auto load_stage = [&](int kt, int buf) {
        uint32_t ab = smem_base + buf * H_STAGE;
        uint32_t bb = ab + H_TILE_B;
        const __half* Asrc = A + (size_t)m0 * K + kt * 32;
        const __half* Bsrc = Bm + (size_t)n0 * K + kt * 32;
#pragma unroll
        for (int j = 0; j < 2; j++) {              // 512 chunks each / 256 thr
            int o = tid + j * 256;
            int r = o >> 2, cc = o & 3;
            cp16(ab + (uint32_t)(r * HROW_B + cc * 16),
                 Asrc + (size_t)r * K + cc * 8);
            cp16(bb + (uint32_t)(r * HROW_B + cc * 16),
                 Bsrc + (size_t)r * K + cc * 8);
        }
    };

    const int wid  = tid >> 5;
    const int lane = tid & 31;
    const int wm = wid & 1;                        // 0..1 (64 rows)
    const int wn = wid >> 1;                       // 0..3 (32 cols)
    const int g  = lane >> 2;
    const int tg = lane & 3;

    // per-lane ldmatrix base offsets (bytes within tile)
    const uint32_t aoff = (uint32_t)((wm * 64 + (lane & 15)) * HROW_B
                                     + ((lane & 16) ? 16 : 0));
    const uint32_t boff = (uint32_t)((wn * 32 + (lane & 7)) * HROW_B
                                     + ((lane & 8) ? 16 : 0));

    float acc[4][4][4];
#pragma unroll
    for (int mi = 0; mi < 4; mi++)
#pragma unroll
        for (int ni = 0; ni < 4; ni++)
#pragma unroll
            for (int q = 0; q < 4; q++) acc[mi][ni][q] = 0.f;

    load_stage(0, 0);
    asm volatile("cp.async.commit_group;" ::: "memory");
    load_stage(1, 1);
    asm volatile("cp.async.commit_group;" ::: "memory");

    for (int kt = 0; kt < KT; kt++) {
        asm volatile("cp.async.wait_group 1;" ::: "memory");
        __syncthreads();

        if (kt + 2 < KT) load_stage(kt + 2, (kt + 2) % H_STAGES);
        asm volatile("cp.async.commit_group;" ::: "memory");

        uint32_t As = smem_base + (kt % H_STAGES) * H_STAGE;
        uint32_t Bs = As + H_TILE_B;

#pragma unroll
        for (int ks = 0; ks < 2; ks++) {
            uint32_t kofs = ks * 32;               // 16 halfs = 32 B
            uint32_t af[4][4];
#pragma unroll
            for (int mi = 0; mi < 4; mi++)
                ldsm_x4(af[mi][0], af[mi][1], af[mi][2], af[mi][3],
                        As + aoff + mi * (16 * HROW_B) + kofs);
            uint32_t bf[4][2];
#pragma unroll
            for (int ni = 0; ni < 4; ni++)
                ldsm_x2(bf[ni][0], bf[ni][1],
                        Bs + boff + ni * (8 * HROW_B) + kofs);
#pragma unroll
            for (int mi = 0; mi < 4; mi++)
#pragma unroll
                for (int ni = 0; ni < 4; ni++)
                    mma_f16(acc[mi][ni], af[mi][0], af[mi][1], af[mi][2],
                            af[mi][3], bf[ni][0], bf[ni][1]);
        }
        __syncthreads();
    }

    // ---- epilogue ----
#pragma unroll
    for (int mi = 0; mi < 4; mi++) {
        int row0 = m0 + wm * 64 + mi * 16 + g;
#pragma unroll
        for (int ni = 0; ni < 4; ni++) {
            int col = n0 + wn * 32 + ni * 8 + tg * 2;
            float2 v0 = make_float2(acc[mi][ni][0], acc[mi][ni][1]);
            float2 v1 = make_float2(acc[mi][ni][2], acc[mi][ni][3]);
            if (BIAS) {
                float2 b2 = *(const float2*)(bias + col);
                v0.x += b2.x; v0.y += b2.y;
                v1.x += b2.x; v1.y += b2.y;
            }
            if (RELU && col < relu_cols) {
                v0.x = fmaxf(v0.x, 0.f); v0.y = fmaxf(v0.y, 0.f);
                v1.x = fmaxf(v1.x, 0.f); v1.y = fmaxf(v1.y, 0.f);
            }
            *(float2*)(C + (size_t)row0 * N + col) = v0;
            *(float2*)(C + (size_t)(row0 + 8) * N + col) = v1;
        }
    }
}

// ------------------------- K4: kv + ksum (split-K partials) -----------------
__global__ __launch_bounds__(256)
void kv_kernel()
{
    int split = blockIdx.x;
    int bh = blockIdx.y;
    int b = bh >> 4, h = bh & 15;
    __shared__ float PK[64][68];
    __shared__ float VV[64][68];
    int tid = threadIdx.x;
    int ti = tid >> 4, tj = tid & 15;

    float acc[4][4];
#pragma unroll
    for (int i = 0; i < 4; i++)
#pragma unroll
        for (int j = 0; j < 4; j++) acc[i][j] = 0.f;
    float ks = 0.f;

    size_t base_row = (size_t)b * 4096 + split * 512;
    for (int c = 0; c < 8; c++) {
#pragma unroll
        for (int i = 0; i < 4; i++) {
            int f = tid + i * 256;
            int r = f >> 4, c4 = (f & 15) << 2;
            const float* src = g_PHIV + (base_row + c * 64 + r) * 3072;
            *(float4*)&PK[r][c4] = *(const float4*)(src + 1024 + h * 64 + c4);
            *(float4*)&VV[r][c4] = *(const float4*)(src + 2048 + h * 64 + c4);
        }
        __syncthreads();
#pragma unroll 8
        for (int n = 0; n < 64; n++) {
            float4 a  = *(float4*)&PK[n][ti * 4];
            float4 bb = *(float4*)&VV[n][tj * 4];
            float av[4] = {a.x, a.y, a.z, a.w};
            float bv[4] = {bb.x, bb.y, bb.z, bb.w};
#pragma unroll
            for (int i = 0; i < 4; i++)
#pragma unroll
                for (int j = 0; j < 4; j++)
                    acc[i][j] += av[i] * bv[j];
        }
        if (tid < 64) {
#pragma unroll 8
            for (int n = 0; n < 64; n++) ks += PK[n][tid];
        }
        __syncthreads();
    }
    float* dst = g_KVP + (size_t)(split * 64 + bh) * 4096;
#pragma unroll
    for (int i = 0; i < 4; i++)
#pragma unroll
        for (int j = 0; j < 4; j++)
            dst[(ti * 4 + i) * 64 + tj * 4 + j] = acc[i][j];
    if (tid < 64) g_KSP[(split * 64 + bh) * 64 + tid] = ks;
}

// ------------------------- K5: deterministic reduction ----------------------
__global__ __launch_bounds__(256)
void kv_reduce_kernel()
{
    int idx = blockIdx.x * 256 + threadIdx.x;
    if (idx < 64 * 4096) {
        int bh = idx >> 12, r = idx & 4095;
        float s = 0.f;
#pragma unroll
        for (int sp = 0; sp < 8; sp++)
            s += g_KVP[(size_t)(sp * 64 + bh) * 4096 + r];
        g_KV[idx] = s;
    } else {
        int j = idx - 64 * 4096;
        if (j < 64 * 64) {
            int bh = j >> 6, d = j & 63;
            float s = 0.f;
#pragma unroll
            for (int sp = 0; sp < 8; sp++)
                s += g_KSP[(sp * 64 + bh) * 64 + d];
            g_KSUM[j] = s;
        }
    }
}

// ------------------------- K6: attn = inv * phiQ @ kv (fp16 out) ------------
__global__ __launch_bounds__(256)
void attn_kernel()
{
    int chunkb = blockIdx.x;
    int bh = blockIdx.y;
    int b = bh >> 4, h = bh & 15;
    __shared__ float KVs[64][64];
    __shared__ float KSs[64];
    int tid = threadIdx.x;
#pragma unroll
    for (int i = 0; i < 4; i++) {
        int f = tid + i * 256;
        *(float4*)&KVs[f >> 4][(f & 15) << 2] =
            *(const float4*)(g_KV + (size_t)bh * 4096 + f * 4);
    }
    if (tid < 64) KSs[tid] = g_KSUM[bh * 64 + tid];
    __syncthreads();

    int r = tid >> 1, halfsel = tid & 1;
    size_t m = (size_t)b * 4096 + chunkb * 128 + r;
    const float* phq = g_PHIV + m * 3072 + h * 64;

    float acc[32];
#pragma unroll
    for (int j = 0; j < 32; j++) acc[j] = 0.f;
    float denom = 0.f;

#pragma unroll
    for (int d0 = 0; d0 < 64; d0 += 16) {
        float q[16];
#pragma unroll
        for (int i = 0; i < 4; i++)
            *(float4*)&q[i * 4] = *(const float4*)(phq + d0 + i * 4);
#pragma unroll
        for (int dd = 0; dd < 16; dd++) {
            int d = d0 + dd;
            float p = q[dd];
            denom += p * KSs[d];
#pragma unroll
            for (int j = 0; j < 32; j += 4) {
                float4 kvv = *(float4*)&KVs[d][halfsel * 32 + j];
                acc[j]     += p * kvv.x;
                acc[j + 1] += p * kvv.y;
                acc[j + 2] += p * kvv.z;
                acc[j + 3] += p * kvv.w;
            }
        }
    }
    float inv = 1.0f / (0.125f * denom + 1e-8f);
    __half* dst = g_ATTNH + m * 1024 + h * 64 + halfsel * 32;
#pragma unroll
    for (int j = 0; j < 32; j += 2)
        *(half2*)(dst + j) = __floats2half2_rn(acc[j] * inv, acc[j + 1] * inv);
}

// ------------------------- launch -------------------------------------------
extern "C" void kernel_launch(void* const* d_in, const int* in_sizes, int n_in,
                              void* d_out, int out_size)
{
    const float* query = (const float*)d_in[0];
    const float* Wq    = (const float*)d_in[1];
    const float* Wk    = (const float*)d_in[2];
    const float* Wv    = (const float*)d_in[3];
    const float* P     = (const float*)d_in[4];
    const float* Wo    = (const float*)d_in[5];
    const float* bo    = (const float*)d_in[6];
    float* out = (float*)d_out;

    void *p_xh, *p_wbigh, *p_worh, *p_attnh, *p_phiv;
    cudaGetSymbolAddress(&p_xh,    g_XH);
    cudaGetSymbolAddress(&p_wbigh, g_WBIGH);
    cudaGetSymbolAddress(&p_worh,  g_WORH);
    cudaGetSymbolAddress(&p_attnh, g_ATTNH);
    cudaGetSymbolAddress(&p_phiv,  g_PHIV);

    cudaFuncSetAttribute(gemm_mma<true, false>,
                         cudaFuncAttributeMaxDynamicSharedMemorySize, GEMM_SMEM);
    cudaFuncSetAttribute(gemm_mma<false, true>,
                         cudaFuncAttributeMaxDynamicSharedMemorySize, GEMM_SMEM);

    build_weff_kernel<<<512, 256>>>(Wq, Wk, P);
    copy_wv_kernel<<<1024, 256>>>(Wv);
    round_half_kernel<<<16384, 256>>>(query, (__half*)p_xh);
    round_half_kernel<<<1024, 256>>>(Wo, (__half*)p_worh);

    // PHIV = relu(XH @ WBIGH^T) on first 2048 cols (fp32 out)
    gemm_mma<true, false><<<dim3(24, 128), 256, GEMM_SMEM>>>(
        (const __half*)p_xh, (const __half*)p_wbigh, nullptr, (float*)p_phiv,
        16384, 3072, 1024, 2048);

    kv_kernel<<<dim3(8, 64), 256>>>();
    kv_reduce_kernel<<<1040, 256>>>();
    attn_kernel<<<dim3(32, 64), 256>>>();   // writes fp16 ATTN

    // out = ATTNH @ WORH^T + bo (fp32 out)
    gemm_mma<false, true><<<dim3(8, 128), 256, GEMM_SMEM>>>(
        (const __half*)p_attnh, (const __half*)p_worh, bo, out,
        16384, 1024, 1024, 0);
}